// round 6
// baseline (speedup 1.0000x reference)
#include <cuda_runtime.h>
#include <math.h>
#include <cstdio>

// Problem shape: N=100000, E=1600000, F=H1=H2=128, C=40
#define NN 100000
#define EE 1600000

__device__ float g_bufA[(size_t)NN * 128];
__device__ float g_bufB[(size_t)NN * 128];
__device__ float g_h3[(size_t)NN * 64];
__device__ float g_dinv[NN];
__device__ int   g_rowptr[NN + 1];
__device__ int   g_cursor[NN];
__device__ int   g_esrc[EE];
__device__ int   g_partials[256];
__device__ int   g_is64;

__device__ unsigned long long g_t0[16];
__device__ unsigned long long g_t1[16];

__device__ __forceinline__ unsigned long long gt_ns() {
    unsigned long long t;
    asm volatile("mov.u64 %0, %%globaltimer;" : "=l"(t));
    return t;
}

__global__ void k_prof_print() {
    if (threadIdx.x == 0 && blockIdx.x == 0) {
        printf("PROF us: hist=%llu scat=%llu g1=%llu a1=%llu g2=%llu a2=%llu g3=%llu a40=%llu\n",
               (g_t1[0] - g_t0[0]) / 1000ull, (g_t1[1] - g_t0[1]) / 1000ull,
               (g_t1[2] - g_t0[2]) / 1000ull, (g_t1[3] - g_t0[3]) / 1000ull,
               (g_t1[4] - g_t0[4]) / 1000ull, (g_t1[5] - g_t0[5]) / 1000ull,
               (g_t1[6] - g_t0[6]) / 1000ull, (g_t1[7] - g_t0[7]) / 1000ull);
    }
}

// ---------------- dtype detect + zero counts + prof reset ----------------
__global__ void k_detect_zero(const int* __restrict__ ei32, int n_check, int N) {
    int i = blockIdx.x * blockDim.x + threadIdx.x;
    if (i < N) g_cursor[i] = 0;
    if (i == 0) {
        int is64 = 1;
        for (int t = 0; t < n_check; t++)
            if (ei32[2 * t + 1] != 0) { is64 = 0; break; }
        g_is64 = is64;
        for (int t = 0; t < 16; t++) { g_t0[t] = ~0ull; g_t1[t] = 0ull; }
    }
}

__device__ __forceinline__ int load_idx(const void* ei, long long pos) {
    return g_is64 ? (int)((const long long*)ei)[pos] : ((const int*)ei)[pos];
}

__global__ void k_hist(const void* __restrict__ ei, int E, int N) {
    if (threadIdx.x == 0) atomicMin(&g_t0[0], gt_ns());
    int e = blockIdx.x * blockDim.x + threadIdx.x;
    if (e < E) {
        int d = load_idx(ei, (long long)E + e);
        if ((unsigned)d < (unsigned)N) atomicAdd(&g_cursor[d], 1);
    }
    if (threadIdx.x == 0) atomicMax(&g_t1[0], gt_ns());
}

__global__ void k_dinv(int N) {
    int i = blockIdx.x * blockDim.x + threadIdx.x;
    if (i < N) g_dinv[i] = rsqrtf((float)(g_cursor[i] + 1));
}

template <int NT>
__device__ __forceinline__ int block_exscan(int v) {
    __shared__ int ws[NT / 32];
    int lane = threadIdx.x & 31, wid = threadIdx.x >> 5;
    int x = v;
#pragma unroll
    for (int o = 1; o < 32; o <<= 1) {
        int y = __shfl_up_sync(0xffffffffu, x, o);
        if (lane >= o) x += y;
    }
    if (lane == 31) ws[wid] = x;
    __syncthreads();
    if (wid == 0) {
        int w = (lane < NT / 32) ? ws[lane] : 0;
#pragma unroll
        for (int o = 1; o < 32; o <<= 1) {
            int y = __shfl_up_sync(0xffffffffu, w, o);
            if (lane >= o) w += y;
        }
        if (lane < NT / 32) ws[lane] = w;
    }
    __syncthreads();
    int base = wid ? ws[wid - 1] : 0;
    return base + x - v;
}

__global__ void k_scan1(int N) {
    int gid = blockIdx.x * 512 + threadIdx.x;
    int v = (gid < N) ? g_cursor[gid] : 0;
    int ex = block_exscan<512>(v);
    if (gid < N) g_rowptr[gid] = ex;
    if (threadIdx.x == 511) g_partials[blockIdx.x] = ex + v;
}

__global__ void k_scan2(int NB) {
    int v = (threadIdx.x < NB) ? g_partials[threadIdx.x] : 0;
    int ex = block_exscan<256>(v);
    if (threadIdx.x < NB) g_partials[threadIdx.x] = ex;
}

__global__ void k_scan3(int N, int E) {
    int gid = blockIdx.x * 512 + threadIdx.x;
    if (gid < N) {
        int r = g_rowptr[gid] + g_partials[blockIdx.x];
        g_rowptr[gid] = r;
        g_cursor[gid] = r;
    }
    if (gid == 0) g_rowptr[N] = E;
}

__global__ void k_scatter(const void* __restrict__ ei, int E, int N) {
    if (threadIdx.x == 0) atomicMin(&g_t0[1], gt_ns());
    int e = blockIdx.x * blockDim.x + threadIdx.x;
    if (e < E) {
        int s = load_idx(ei, e);
        int d = load_idx(ei, (long long)E + e);
        if ((unsigned)d < (unsigned)N && (unsigned)s < (unsigned)N) {
            int p = atomicAdd(&g_cursor[d], 1);
            if ((unsigned)p < (unsigned)EE) g_esrc[p] = s;
        }
    }
    if (threadIdx.x == 0) atomicMax(&g_t1[1], gt_ns());
}

// ---------------- GEMM: C[N,BN] = A[N,128] @ W[128,KW] ----------------
// 64xBN tile, 256 threads (16x16), 4xTN micro-tile, K chunk 32, 3 blocks/SM.
template <int BN, int TN>
__global__ __launch_bounds__(256, 3) void k_gemm(const float* __restrict__ A,
                                                 const float* __restrict__ W,
                                                 float* __restrict__ C, int N, int KW,
                                                 int slot) {
    if (threadIdx.x == 0) atomicMin(&g_t0[slot], gt_ns());
    __shared__ float As[64 * 36];         // [row][k], pad 36
    __shared__ float Ws[32 * (BN + 4)];   // [k][c]
    const int WSP = BN + 4;
    int tid = threadIdx.x;
    int tx = tid & 15, ty = tid >> 4;
    int m0 = blockIdx.x * 64;

    float acc[4][TN];
#pragma unroll
    for (int i = 0; i < 4; i++)
#pragma unroll
        for (int j = 0; j < TN; j++) acc[i][j] = 0.f;

    for (int kc = 0; kc < 128; kc += 32) {
#pragma unroll
        for (int t = 0; t < 2; t++) {
            int idx = tid + t * 256;
            int r = idx >> 3;
            int c4 = (idx & 7) * 4;
            float4 v = make_float4(0.f, 0.f, 0.f, 0.f);
            if (m0 + r < N)
                v = *(const float4*)(A + (size_t)(m0 + r) * 128 + kc + c4);
            *(float4*)&As[r * 36 + c4] = v;
        }
        if (KW == BN) {
#pragma unroll
            for (int t = 0; t < (32 * BN) / 1024; t++) {
                int idx = tid + t * 256;
                int k = idx / (BN / 4);
                int c4 = (idx % (BN / 4)) * 4;
                float4 v = *(const float4*)(W + (size_t)(kc + k) * KW + c4);
                *(float4*)&Ws[k * WSP + c4] = v;
            }
        } else {
#pragma unroll
            for (int t = 0; t < (32 * BN) / 256; t++) {
                int idx = tid + t * 256;
                int k = idx / BN, c = idx % BN;
                Ws[k * WSP + c] = (c < KW) ? W[(size_t)(kc + k) * KW + c] : 0.f;
            }
        }
        __syncthreads();
#pragma unroll 4
        for (int k = 0; k < 32; k++) {
            float a[4];
#pragma unroll
            for (int i = 0; i < 4; i++) a[i] = As[(ty * 4 + i) * 36 + k];
            float w[TN];
#pragma unroll
            for (int q = 0; q < TN; q += 4) {
                float4 wv = *(const float4*)&Ws[k * WSP + tx * TN + q];
                w[q] = wv.x; w[q + 1] = wv.y; w[q + 2] = wv.z; w[q + 3] = wv.w;
            }
#pragma unroll
            for (int i = 0; i < 4; i++)
#pragma unroll
                for (int j = 0; j < TN; j++) acc[i][j] += a[i] * w[j];
        }
        __syncthreads();
    }
#pragma unroll
    for (int i = 0; i < 4; i++) {
        int r = m0 + ty * 4 + i;
        if (r < N) {
            float* cp = C + (size_t)r * BN + tx * TN;
#pragma unroll
            for (int j = 0; j < TN; j += 4)
                *(float4*)(cp + j) =
                    make_float4(acc[i][j], acc[i][j + 1], acc[i][j + 2], acc[i][j + 3]);
        }
    }
    if (threadIdx.x == 0) atomicMax(&g_t1[slot], gt_ns());
}

// ---------------- Aggregation (128 feat): warp per dst node ----------------
__global__ __launch_bounds__(256) void k_agg128(const float* __restrict__ h,
                                                const float* __restrict__ bias,
                                                float* __restrict__ out, int N,
                                                int do_relu, int slot) {
    if (threadIdx.x == 0) atomicMin(&g_t0[slot], gt_ns());
    int node = (blockIdx.x * blockDim.x + threadIdx.x) >> 5;
    if (node < N) {
        int lane = threadIdx.x & 31;
        const float4* h4 = (const float4*)h;
        int beg = g_rowptr[node], end = g_rowptr[node + 1];

        float ax = 0, ay = 0, az = 0, aw = 0;
        float bx = 0, by = 0, bz = 0, bw = 0;
        int e = beg;
        for (; e + 4 <= end; e += 4) {
            int s0 = g_esrc[e], s1 = g_esrc[e + 1];
            int s2 = g_esrc[e + 2], s3 = g_esrc[e + 3];
            float w0 = g_dinv[s0], w1 = g_dinv[s1];
            float w2 = g_dinv[s2], w3 = g_dinv[s3];
            float4 v0 = h4[(size_t)s0 * 32 + lane];
            float4 v1 = h4[(size_t)s1 * 32 + lane];
            float4 v2 = h4[(size_t)s2 * 32 + lane];
            float4 v3 = h4[(size_t)s3 * 32 + lane];
            ax += w0 * v0.x; ay += w0 * v0.y; az += w0 * v0.z; aw += w0 * v0.w;
            bx += w1 * v1.x; by += w1 * v1.y; bz += w1 * v1.z; bw += w1 * v1.w;
            ax += w2 * v2.x; ay += w2 * v2.y; az += w2 * v2.z; aw += w2 * v2.w;
            bx += w3 * v3.x; by += w3 * v3.y; bz += w3 * v3.z; bw += w3 * v3.w;
        }
        for (; e < end; e++) {
            int s0 = g_esrc[e];
            float w0 = g_dinv[s0];
            float4 v0 = h4[(size_t)s0 * 32 + lane];
            ax += w0 * v0.x; ay += w0 * v0.y; az += w0 * v0.z; aw += w0 * v0.w;
        }
        float dd = g_dinv[node];
        float4 vs = h4[(size_t)node * 32 + lane];
        ax += bx + dd * vs.x;
        ay += by + dd * vs.y;
        az += bz + dd * vs.z;
        aw += bw + dd * vs.w;
        float4 bb = ((const float4*)bias)[lane];
        float4 o;
        o.x = dd * ax + bb.x;
        o.y = dd * ay + bb.y;
        o.z = dd * az + bb.z;
        o.w = dd * aw + bb.w;
        if (do_relu) {
            o.x = fmaxf(o.x, 0.f); o.y = fmaxf(o.y, 0.f);
            o.z = fmaxf(o.z, 0.f); o.w = fmaxf(o.w, 0.f);
        }
        ((float4*)out)[(size_t)node * 32 + lane] = o;
    }
    if (threadIdx.x == 0) atomicMax(&g_t1[slot], gt_ns());
}

// ---------------- Aggregation (40 feat, stride 64) + fused log_softmax ----------------
__global__ __launch_bounds__(256) void k_agg40(const float* __restrict__ h,
                                               const float* __restrict__ bias,
                                               float* __restrict__ out, int N) {
    if (threadIdx.x == 0) atomicMin(&g_t0[7], gt_ns());
    int node = (blockIdx.x * blockDim.x + threadIdx.x) >> 5;
    if (node < N) {
        int lane = threadIdx.x & 31;
        int beg = g_rowptr[node], end = g_rowptr[node + 1];
        float a0 = 0.f, a1 = 0.f;
        for (int e = beg; e < end; e++) {
            int s = g_esrc[e];
            float wv = g_dinv[s];
            const float* hp = h + (size_t)s * 64;
            a0 += wv * hp[lane];
            a1 += wv * hp[32 + lane];
        }
        float dd = g_dinv[node];
        const float* hs = h + (size_t)node * 64;
        a0 += dd * hs[lane];
        a1 += dd * hs[32 + lane];
        float l0 = dd * a0 + bias[lane];
        float l1 = -3.4e38f;
        if (lane < 8) l1 = dd * a1 + bias[32 + lane];
        float m = fmaxf(l0, l1);
#pragma unroll
        for (int o = 16; o; o >>= 1) m = fmaxf(m, __shfl_xor_sync(0xffffffffu, m, o));
        float s = expf(l0 - m) + ((lane < 8) ? expf(l1 - m) : 0.f);
#pragma unroll
        for (int o = 16; o; o >>= 1) s += __shfl_xor_sync(0xffffffffu, s, o);
        float ls = logf(s);
        out[(size_t)node * 40 + lane] = l0 - m - ls;
        if (lane < 8) out[(size_t)node * 40 + 32 + lane] = l1 - m - ls;
    }
    if (threadIdx.x == 0) atomicMax(&g_t1[7], gt_ns());
}

// ---------------- host launcher ----------------
// EXPERIMENT: run the entire (idempotent) pipeline TWICE with identical kernels.
// dur_us(this round) - 12434us  ==  true marginal cost of one full pipeline pass.
extern "C" void kernel_launch(void* const* d_in, const int* in_sizes, int n_in,
                              void* d_out, int out_size) {
    const float* x = (const float*)d_in[0];
    const void* ei = d_in[1];
    const float* W1 = (const float*)d_in[2];
    const float* b1 = (const float*)d_in[3];
    const float* W2 = (const float*)d_in[4];
    const float* b2 = (const float*)d_in[5];
    const float* W3 = (const float*)d_in[6];
    const float* b3 = (const float*)d_in[7];

    int N = in_sizes[0] / 128;
    int E = in_sizes[1] / 2;

    int NB = (N + 511) / 512;
    int EB = (E + 255) / 256;
    int GB = (N + 63) / 64;
    int AB = (N + 7) / 8;

    for (int rep = 0; rep < 2; rep++) {
        k_detect_zero<<<NB, 512>>>((const int*)ei, 64, N);
        k_hist<<<EB, 256>>>(ei, E, N);
        k_dinv<<<NB, 512>>>(N);
        k_gemm<128, 8><<<GB, 256>>>(x, W1, g_bufA, N, 128, 2);   // ncu slot (launch #4)
        k_scan1<<<NB, 512>>>(N);
        k_scan2<<<1, 256>>>(NB);
        k_scan3<<<NB, 512>>>(N, E);
        k_scatter<<<EB, 256>>>(ei, E, N);

        k_agg128<<<AB, 256>>>(g_bufA, b1, g_bufB, N, 1, 3);
        k_gemm<128, 8><<<GB, 256>>>(g_bufB, W2, g_bufA, N, 128, 4);
        k_agg128<<<AB, 256>>>(g_bufA, b2, g_bufB, N, 1, 5);
        k_gemm<64, 4><<<GB, 256>>>(g_bufB, W3, g_h3, N, 40, 6);
        k_agg40<<<AB, 256>>>(g_h3, b3, (float*)d_out, N);
    }
    k_prof_print<<<1, 32>>>();
}

// round 7
// speedup vs baseline: 1.4948x; 1.4948x over previous
#include <cuda_runtime.h>
#include <math.h>
#include <cstdio>

// Problem shape: N=100000, E=1600000, F=H1=H2=128, C=40
#define NN 100000
#define EE 1600000

__device__ float g_bufA[(size_t)NN * 128];
__device__ float g_bufB[(size_t)NN * 128];
__device__ float g_h3[(size_t)NN * 64];
__device__ float g_dinv[NN];
__device__ int   g_rowptr[NN + 1];
__device__ int   g_cursor[NN];
__device__ int   g_esrc[EE];
__device__ int   g_partials[256];
__device__ int   g_is64;

__device__ unsigned long long g_t0[16];
__device__ unsigned long long g_t1[16];

__device__ __forceinline__ unsigned long long gt_ns() {
    unsigned long long t;
    asm volatile("mov.u64 %0, %%globaltimer;" : "=l"(t));
    return t;
}

__global__ void k_prof_print() {
    if (threadIdx.x == 0 && blockIdx.x == 0) {
        printf("PROF us: hist=%llu scat=%llu g1=%llu a1=%llu g2=%llu a2=%llu g3=%llu a40=%llu dummyagg=%llu\n",
               (g_t1[0] - g_t0[0]) / 1000ull, (g_t1[1] - g_t0[1]) / 1000ull,
               (g_t1[2] - g_t0[2]) / 1000ull, (g_t1[3] - g_t0[3]) / 1000ull,
               (g_t1[4] - g_t0[4]) / 1000ull, (g_t1[5] - g_t0[5]) / 1000ull,
               (g_t1[6] - g_t0[6]) / 1000ull, (g_t1[7] - g_t0[7]) / 1000ull,
               (g_t1[8] - g_t0[8]) / 1000ull);
    }
}

// ---------------- dtype detect + zero counts + prof reset ----------------
__global__ void k_detect_zero(const int* __restrict__ ei32, int n_check, int N) {
    int i = blockIdx.x * blockDim.x + threadIdx.x;
    if (i < N) g_cursor[i] = 0;
    if (i == 0) {
        int is64 = 1;
        for (int t = 0; t < n_check; t++)
            if (ei32[2 * t + 1] != 0) { is64 = 0; break; }
        g_is64 = is64;
        for (int t = 0; t < 16; t++) { g_t0[t] = ~0ull; g_t1[t] = 0ull; }
    }
}

__device__ __forceinline__ int load_idx(const void* ei, long long pos) {
    return g_is64 ? (int)((const long long*)ei)[pos] : ((const int*)ei)[pos];
}

__global__ void k_hist(const void* __restrict__ ei, int E, int N) {
    if (threadIdx.x == 0) atomicMin(&g_t0[0], gt_ns());
    int e = blockIdx.x * blockDim.x + threadIdx.x;
    if (e < E) {
        int d = load_idx(ei, (long long)E + e);
        if ((unsigned)d < (unsigned)N) atomicAdd(&g_cursor[d], 1);
    }
    if (threadIdx.x == 0) atomicMax(&g_t1[0], gt_ns());
}

__global__ void k_dinv(int N) {
    int i = blockIdx.x * blockDim.x + threadIdx.x;
    if (i < N) g_dinv[i] = rsqrtf((float)(g_cursor[i] + 1));
}

template <int NT>
__device__ __forceinline__ int block_exscan(int v) {
    __shared__ int ws[NT / 32];
    int lane = threadIdx.x & 31, wid = threadIdx.x >> 5;
    int x = v;
#pragma unroll
    for (int o = 1; o < 32; o <<= 1) {
        int y = __shfl_up_sync(0xffffffffu, x, o);
        if (lane >= o) x += y;
    }
    if (lane == 31) ws[wid] = x;
    __syncthreads();
    if (wid == 0) {
        int w = (lane < NT / 32) ? ws[lane] : 0;
#pragma unroll
        for (int o = 1; o < 32; o <<= 1) {
            int y = __shfl_up_sync(0xffffffffu, w, o);
            if (lane >= o) w += y;
        }
        if (lane < NT / 32) ws[lane] = w;
    }
    __syncthreads();
    int base = wid ? ws[wid - 1] : 0;
    return base + x - v;
}

__global__ void k_scan1(int N) {
    int gid = blockIdx.x * 512 + threadIdx.x;
    int v = (gid < N) ? g_cursor[gid] : 0;
    int ex = block_exscan<512>(v);
    if (gid < N) g_rowptr[gid] = ex;
    if (threadIdx.x == 511) g_partials[blockIdx.x] = ex + v;
}

__global__ void k_scan2(int NB) {
    int v = (threadIdx.x < NB) ? g_partials[threadIdx.x] : 0;
    int ex = block_exscan<256>(v);
    if (threadIdx.x < NB) g_partials[threadIdx.x] = ex;
}

__global__ void k_scan3(int N, int E) {
    int gid = blockIdx.x * 512 + threadIdx.x;
    if (gid < N) {
        int r = g_rowptr[gid] + g_partials[blockIdx.x];
        g_rowptr[gid] = r;
        g_cursor[gid] = r;
    }
    if (gid == 0) g_rowptr[N] = E;
}

__global__ void k_scatter(const void* __restrict__ ei, int E, int N) {
    if (threadIdx.x == 0) atomicMin(&g_t0[1], gt_ns());
    int e = blockIdx.x * blockDim.x + threadIdx.x;
    if (e < E) {
        int s = load_idx(ei, e);
        int d = load_idx(ei, (long long)E + e);
        if ((unsigned)d < (unsigned)N && (unsigned)s < (unsigned)N) {
            int p = atomicAdd(&g_cursor[d], 1);
            if ((unsigned)p < (unsigned)EE) g_esrc[p] = s;
        }
    }
    if (threadIdx.x == 0) atomicMax(&g_t1[1], gt_ns());
}

// ---------------- GEMM: C[N,BN] = A[N,128] @ W[128,KW] ----------------
template <int BN, int TN>
__global__ __launch_bounds__(256, 3) void k_gemm(const float* __restrict__ A,
                                                 const float* __restrict__ W,
                                                 float* __restrict__ C, int N, int KW,
                                                 int slot) {
    if (threadIdx.x == 0) atomicMin(&g_t0[slot], gt_ns());
    __shared__ float As[64 * 36];
    __shared__ float Ws[32 * (BN + 4)];
    const int WSP = BN + 4;
    int tid = threadIdx.x;
    int tx = tid & 15, ty = tid >> 4;
    int m0 = blockIdx.x * 64;

    float acc[4][TN];
#pragma unroll
    for (int i = 0; i < 4; i++)
#pragma unroll
        for (int j = 0; j < TN; j++) acc[i][j] = 0.f;

    for (int kc = 0; kc < 128; kc += 32) {
#pragma unroll
        for (int t = 0; t < 2; t++) {
            int idx = tid + t * 256;
            int r = idx >> 3;
            int c4 = (idx & 7) * 4;
            float4 v = make_float4(0.f, 0.f, 0.f, 0.f);
            if (m0 + r < N)
                v = *(const float4*)(A + (size_t)(m0 + r) * 128 + kc + c4);
            *(float4*)&As[r * 36 + c4] = v;
        }
        if (KW == BN) {
#pragma unroll
            for (int t = 0; t < (32 * BN) / 1024; t++) {
                int idx = tid + t * 256;
                int k = idx / (BN / 4);
                int c4 = (idx % (BN / 4)) * 4;
                float4 v = *(const float4*)(W + (size_t)(kc + k) * KW + c4);
                *(float4*)&Ws[k * WSP + c4] = v;
            }
        } else {
#pragma unroll
            for (int t = 0; t < (32 * BN) / 256; t++) {
                int idx = tid + t * 256;
                int k = idx / BN, c = idx % BN;
                Ws[k * WSP + c] = (c < KW) ? W[(size_t)(kc + k) * KW + c] : 0.f;
            }
        }
        __syncthreads();
#pragma unroll 4
        for (int k = 0; k < 32; k++) {
            float a[4];
#pragma unroll
            for (int i = 0; i < 4; i++) a[i] = As[(ty * 4 + i) * 36 + k];
            float w[TN];
#pragma unroll
            for (int q = 0; q < TN; q += 4) {
                float4 wv = *(const float4*)&Ws[k * WSP + tx * TN + q];
                w[q] = wv.x; w[q + 1] = wv.y; w[q + 2] = wv.z; w[q + 3] = wv.w;
            }
#pragma unroll
            for (int i = 0; i < 4; i++)
#pragma unroll
                for (int j = 0; j < TN; j++) acc[i][j] += a[i] * w[j];
        }
        __syncthreads();
    }
#pragma unroll
    for (int i = 0; i < 4; i++) {
        int r = m0 + ty * 4 + i;
        if (r < N) {
            float* cp = C + (size_t)r * BN + tx * TN;
#pragma unroll
            for (int j = 0; j < TN; j += 4)
                *(float4*)(cp + j) =
                    make_float4(acc[i][j], acc[i][j + 1], acc[i][j + 2], acc[i][j + 3]);
        }
    }
    if (threadIdx.x == 0) atomicMax(&g_t1[slot], gt_ns());
}

// ---------------- Aggregation (128 feat): warp per dst node, 8-edge MLP ----------------
__global__ __launch_bounds__(256) void k_agg128(const float* __restrict__ h,
                                                const float* __restrict__ bias,
                                                float* __restrict__ out, int N,
                                                int do_relu, int slot) {
    if (threadIdx.x == 0) atomicMin(&g_t0[slot], gt_ns());
    int node = (blockIdx.x * blockDim.x + threadIdx.x) >> 5;
    if (node < N) {
        int lane = threadIdx.x & 31;
        const float4* h4 = (const float4*)h;
        int beg = g_rowptr[node], end = g_rowptr[node + 1];

        float ax = 0, ay = 0, az = 0, aw = 0;
        float bx = 0, by = 0, bz = 0, bw = 0;
        int e = beg;
        for (; e + 8 <= end; e += 8) {
            int s[8];
#pragma unroll
            for (int q = 0; q < 8; q++) s[q] = g_esrc[e + q];
            float wgt[8];
#pragma unroll
            for (int q = 0; q < 8; q++) wgt[q] = g_dinv[s[q]];
            float4 v[8];
#pragma unroll
            for (int q = 0; q < 8; q++) v[q] = h4[(size_t)s[q] * 32 + lane];
#pragma unroll
            for (int q = 0; q < 8; q += 2) {
                ax += wgt[q] * v[q].x; ay += wgt[q] * v[q].y;
                az += wgt[q] * v[q].z; aw += wgt[q] * v[q].w;
                bx += wgt[q + 1] * v[q + 1].x; by += wgt[q + 1] * v[q + 1].y;
                bz += wgt[q + 1] * v[q + 1].z; bw += wgt[q + 1] * v[q + 1].w;
            }
        }
        for (; e < end; e++) {
            int s0 = g_esrc[e];
            float w0 = g_dinv[s0];
            float4 v0 = h4[(size_t)s0 * 32 + lane];
            ax += w0 * v0.x; ay += w0 * v0.y; az += w0 * v0.z; aw += w0 * v0.w;
        }
        float dd = g_dinv[node];
        float4 vs = h4[(size_t)node * 32 + lane];
        ax += bx + dd * vs.x;
        ay += by + dd * vs.y;
        az += bz + dd * vs.z;
        aw += bw + dd * vs.w;
        float4 bb = ((const float4*)bias)[lane];
        float4 o;
        o.x = dd * ax + bb.x;
        o.y = dd * ay + bb.y;
        o.z = dd * az + bb.z;
        o.w = dd * aw + bb.w;
        if (do_relu) {
            o.x = fmaxf(o.x, 0.f); o.y = fmaxf(o.y, 0.f);
            o.z = fmaxf(o.z, 0.f); o.w = fmaxf(o.w, 0.f);
        }
        ((float4*)out)[(size_t)node * 32 + lane] = o;
    }
    if (threadIdx.x == 0) atomicMax(&g_t1[slot], gt_ns());
}

// ---------------- Aggregation (40 feat, stride 64) + fused log_softmax ----------------
__global__ __launch_bounds__(256) void k_agg40(const float* __restrict__ h,
                                               const float* __restrict__ bias,
                                               float* __restrict__ out, int N) {
    if (threadIdx.x == 0) atomicMin(&g_t0[7], gt_ns());
    int node = (blockIdx.x * blockDim.x + threadIdx.x) >> 5;
    if (node < N) {
        int lane = threadIdx.x & 31;
        int beg = g_rowptr[node], end = g_rowptr[node + 1];
        float a0 = 0.f, a1 = 0.f;
        for (int e = beg; e < end; e++) {
            int s = g_esrc[e];
            float wv = g_dinv[s];
            const float* hp = h + (size_t)s * 64;
            a0 += wv * hp[lane];
            a1 += wv * hp[32 + lane];
        }
        float dd = g_dinv[node];
        const float* hs = h + (size_t)node * 64;
        a0 += dd * hs[lane];
        a1 += dd * hs[32 + lane];
        float l0 = dd * a0 + bias[lane];
        float l1 = -3.4e38f;
        if (lane < 8) l1 = dd * a1 + bias[32 + lane];
        float m = fmaxf(l0, l1);
#pragma unroll
        for (int o = 16; o; o >>= 1) m = fmaxf(m, __shfl_xor_sync(0xffffffffu, m, o));
        float s = expf(l0 - m) + ((lane < 8) ? expf(l1 - m) : 0.f);
#pragma unroll
        for (int o = 16; o; o >>= 1) s += __shfl_xor_sync(0xffffffffu, s, o);
        float ls = logf(s);
        out[(size_t)node * 40 + lane] = l0 - m - ls;
        if (lane < 8) out[(size_t)node * 40 + 32 + lane] = l1 - m - ls;
    }
    if (threadIdx.x == 0) atomicMax(&g_t1[7], gt_ns());
}

// ---------------- host launcher ----------------
// Launch #4 (the ncu capture slot) = DUMMY agg128 reading the CSR persisted from
// the previous replay (device globals persist; first call they are zero -> no-op).
// Its output buffer is overwritten by the real pipeline afterwards, so d_out is
// unaffected and deterministic. dur(R7) - 12434us ~= t_agg128.
extern "C" void kernel_launch(void* const* d_in, const int* in_sizes, int n_in,
                              void* d_out, int out_size) {
    const float* x = (const float*)d_in[0];
    const void* ei = d_in[1];
    const float* W1 = (const float*)d_in[2];
    const float* b1 = (const float*)d_in[3];
    const float* W2 = (const float*)d_in[4];
    const float* b2 = (const float*)d_in[5];
    const float* W3 = (const float*)d_in[6];
    const float* b3 = (const float*)d_in[7];

    int N = in_sizes[0] / 128;
    int E = in_sizes[1] / 2;

    int NB = (N + 511) / 512;
    int EB = (E + 255) / 256;
    int GB = (N + 63) / 64;
    int AB = (N + 7) / 8;

    k_detect_zero<<<NB, 512>>>((const int*)ei, 64, N);
    k_hist<<<EB, 256>>>(ei, E, N);
    k_dinv<<<NB, 512>>>(N);
    k_agg128<<<AB, 256>>>(g_bufA, b1, g_bufB, N, 1, 8);   // DUMMY - profiled slot
    k_scan1<<<NB, 512>>>(N);
    k_scan2<<<1, 256>>>(NB);
    k_scan3<<<NB, 512>>>(N, E);
    k_scatter<<<EB, 256>>>(ei, E, N);

    k_gemm<128, 8><<<GB, 256>>>(x, W1, g_bufA, N, 128, 2);
    k_agg128<<<AB, 256>>>(g_bufA, b1, g_bufB, N, 1, 3);
    k_gemm<128, 8><<<GB, 256>>>(g_bufB, W2, g_bufA, N, 128, 4);
    k_agg128<<<AB, 256>>>(g_bufA, b2, g_bufB, N, 1, 5);
    k_gemm<64, 4><<<GB, 256>>>(g_bufB, W3, g_h3, N, 40, 6);
    k_agg40<<<AB, 256>>>(g_h3, b3, (float*)d_out, N);
    k_prof_print<<<1, 32>>>();
}

// round 8
// speedup vs baseline: 2.7318x; 1.8275x over previous
#include <cuda_runtime.h>
#include <cuda_fp16.h>
#include <math.h>
#include <cstdio>

// Problem shape: N=100000, E=1600000, F=H1=H2=128, C=40
#define NN 100000
#define EE 1600000

__device__ __half g_hA[(size_t)NN * 128];   // half feature buffer (gemm1/gemm2 out)
__device__ float  g_bufB[(size_t)NN * 128]; // fp32 agg output (gemm input)
__device__ __half g_h3h[(size_t)NN * 64];   // layer-3 gemm out, half, padded 40->64
__device__ float  g_dinv[NN];
__device__ int    g_rowptr[NN + 1];
__device__ int    g_cursor[NN];
__device__ int    g_esrc[EE];
__device__ int    g_partials[256];
__device__ int    g_is64;

__device__ unsigned long long g_t0[16];
__device__ unsigned long long g_t1[16];

__device__ __forceinline__ unsigned long long gt_ns() {
    unsigned long long t;
    asm volatile("mov.u64 %0, %%globaltimer;" : "=l"(t));
    return t;
}

__global__ void k_prof_print() {
    if (threadIdx.x == 0 && blockIdx.x == 0) {
        printf("PROF us: hist=%llu scat=%llu g1=%llu a1=%llu g2=%llu a2=%llu g3=%llu a40=%llu synth=%llu\n",
               (g_t1[0] - g_t0[0]) / 1000ull, (g_t1[1] - g_t0[1]) / 1000ull,
               (g_t1[2] - g_t0[2]) / 1000ull, (g_t1[3] - g_t0[3]) / 1000ull,
               (g_t1[4] - g_t0[4]) / 1000ull, (g_t1[5] - g_t0[5]) / 1000ull,
               (g_t1[6] - g_t0[6]) / 1000ull, (g_t1[7] - g_t0[7]) / 1000ull,
               (g_t1[8] - g_t0[8]) / 1000ull);
    }
}

// ---------------- dtype detect + zero counts + prof reset ----------------
__global__ void k_detect_zero(const int* __restrict__ ei32, int n_check, int N) {
    int i = blockIdx.x * blockDim.x + threadIdx.x;
    if (i < N) g_cursor[i] = 0;
    if (i == 0) {
        int is64 = 1;
        for (int t = 0; t < n_check; t++)
            if (ei32[2 * t + 1] != 0) { is64 = 0; break; }
        g_is64 = is64;
        for (int t = 0; t < 16; t++) { g_t0[t] = ~0ull; g_t1[t] = 0ull; }
    }
}

__device__ __forceinline__ int load_idx(const void* ei, long long pos) {
    return g_is64 ? (int)((const long long*)ei)[pos] : ((const int*)ei)[pos];
}

__global__ void k_hist(const void* __restrict__ ei, int E, int N) {
    if (threadIdx.x == 0) atomicMin(&g_t0[0], gt_ns());
    int e = blockIdx.x * blockDim.x + threadIdx.x;
    if (e < E) {
        int d = load_idx(ei, (long long)E + e);
        if ((unsigned)d < (unsigned)N) atomicAdd(&g_cursor[d], 1);
    }
    if (threadIdx.x == 0) atomicMax(&g_t1[0], gt_ns());
}

__global__ void k_dinv(int N) {
    int i = blockIdx.x * blockDim.x + threadIdx.x;
    if (i < N) g_dinv[i] = rsqrtf((float)(g_cursor[i] + 1));
}

// ---------------- synthetic gather probe (ncu capture slot #4) ----------------
// Hash-indexed half-row gather with identical memory shape to k_agg128.
// Output buffer g_bufB is fully overwritten by the real pipeline afterwards.
__global__ __launch_bounds__(256) void k_synth_gather(const __half* __restrict__ h,
                                                      float* __restrict__ out, int N) {
    if (threadIdx.x == 0) atomicMin(&g_t0[8], gt_ns());
    int node = (blockIdx.x * blockDim.x + threadIdx.x) >> 5;
    if (node < N) {
        int lane = threadIdx.x & 31;
        const uint2* h2 = (const uint2*)h;
        unsigned base = (unsigned)node * 2654435761u;
        float ax = 0, ay = 0, az = 0, aw = 0;
        uint2 raw[8];
#pragma unroll
        for (int q = 0; q < 8; q++) {
            unsigned s = (base + (unsigned)q * 40503u) % (unsigned)N;
            raw[q] = h2[(size_t)s * 32 + lane];
        }
#pragma unroll
        for (int q = 0; q < 8; q++) {
            float2 f0 = __half22float2(*(__half2*)&raw[q].x);
            float2 f1 = __half22float2(*(__half2*)&raw[q].y);
            ax += f0.x; ay += f0.y; az += f1.x; aw += f1.y;
        }
        ((float4*)out)[(size_t)node * 32 + lane] = make_float4(ax, ay, az, aw);
    }
    if (threadIdx.x == 0) atomicMax(&g_t1[8], gt_ns());
}

template <int NT>
__device__ __forceinline__ int block_exscan(int v) {
    __shared__ int ws[NT / 32];
    int lane = threadIdx.x & 31, wid = threadIdx.x >> 5;
    int x = v;
#pragma unroll
    for (int o = 1; o < 32; o <<= 1) {
        int y = __shfl_up_sync(0xffffffffu, x, o);
        if (lane >= o) x += y;
    }
    if (lane == 31) ws[wid] = x;
    __syncthreads();
    if (wid == 0) {
        int w = (lane < NT / 32) ? ws[lane] : 0;
#pragma unroll
        for (int o = 1; o < 32; o <<= 1) {
            int y = __shfl_up_sync(0xffffffffu, w, o);
            if (lane >= o) w += y;
        }
        if (lane < NT / 32) ws[lane] = w;
    }
    __syncthreads();
    int base = wid ? ws[wid - 1] : 0;
    return base + x - v;
}

__global__ void k_scan1(int N) {
    int gid = blockIdx.x * 512 + threadIdx.x;
    int v = (gid < N) ? g_cursor[gid] : 0;
    int ex = block_exscan<512>(v);
    if (gid < N) g_rowptr[gid] = ex;
    if (threadIdx.x == 511) g_partials[blockIdx.x] = ex + v;
}

__global__ void k_scan2(int NB) {
    int v = (threadIdx.x < NB) ? g_partials[threadIdx.x] : 0;
    int ex = block_exscan<256>(v);
    if (threadIdx.x < NB) g_partials[threadIdx.x] = ex;
}

__global__ void k_scan3(int N, int E) {
    int gid = blockIdx.x * 512 + threadIdx.x;
    if (gid < N) {
        int r = g_rowptr[gid] + g_partials[blockIdx.x];
        g_rowptr[gid] = r;
        g_cursor[gid] = r;
    }
    if (gid == 0) g_rowptr[N] = E;
}

__global__ void k_scatter(const void* __restrict__ ei, int E, int N) {
    if (threadIdx.x == 0) atomicMin(&g_t0[1], gt_ns());
    int e = blockIdx.x * blockDim.x + threadIdx.x;
    if (e < E) {
        int s = load_idx(ei, e);
        int d = load_idx(ei, (long long)E + e);
        if ((unsigned)d < (unsigned)N && (unsigned)s < (unsigned)N) {
            int p = atomicAdd(&g_cursor[d], 1);
            if ((unsigned)p < (unsigned)EE) g_esrc[p] = s;
        }
    }
    if (threadIdx.x == 0) atomicMax(&g_t1[1], gt_ns());
}

// ---------------- GEMM: C_half[N,BN] = A_f32[N,128] @ W[128,KW] ----------------
// 64xBN tile, 256 threads, 4xTN micro-tile, fp32 accumulate, half output.
template <int BN, int TN>
__global__ __launch_bounds__(256, 3) void k_gemm(const float* __restrict__ A,
                                                 const float* __restrict__ W,
                                                 __half* __restrict__ C, int N, int KW,
                                                 int slot) {
    if (threadIdx.x == 0) atomicMin(&g_t0[slot], gt_ns());
    __shared__ float As[64 * 36];
    __shared__ float Ws[32 * (BN + 4)];
    const int WSP = BN + 4;
    int tid = threadIdx.x;
    int tx = tid & 15, ty = tid >> 4;
    int m0 = blockIdx.x * 64;

    float acc[4][TN];
#pragma unroll
    for (int i = 0; i < 4; i++)
#pragma unroll
        for (int j = 0; j < TN; j++) acc[i][j] = 0.f;

    for (int kc = 0; kc < 128; kc += 32) {
#pragma unroll
        for (int t = 0; t < 2; t++) {
            int idx = tid + t * 256;
            int r = idx >> 3;
            int c4 = (idx & 7) * 4;
            float4 v = make_float4(0.f, 0.f, 0.f, 0.f);
            if (m0 + r < N)
                v = *(const float4*)(A + (size_t)(m0 + r) * 128 + kc + c4);
            *(float4*)&As[r * 36 + c4] = v;
        }
        if (KW == BN) {
#pragma unroll
            for (int t = 0; t < (32 * BN) / 1024; t++) {
                int idx = tid + t * 256;
                int k = idx / (BN / 4);
                int c4 = (idx % (BN / 4)) * 4;
                float4 v = *(const float4*)(W + (size_t)(kc + k) * KW + c4);
                *(float4*)&Ws[k * WSP + c4] = v;
            }
        } else {
#pragma unroll
            for (int t = 0; t < (32 * BN) / 256; t++) {
                int idx = tid + t * 256;
                int k = idx / BN, c = idx % BN;
                Ws[k * WSP + c] = (c < KW) ? W[(size_t)(kc + k) * KW + c] : 0.f;
            }
        }
        __syncthreads();
#pragma unroll 4
        for (int k = 0; k < 32; k++) {
            float a[4];
#pragma unroll
            for (int i = 0; i < 4; i++) a[i] = As[(ty * 4 + i) * 36 + k];
            float w[TN];
#pragma unroll
            for (int q = 0; q < TN; q += 4) {
                float4 wv = *(const float4*)&Ws[k * WSP + tx * TN + q];
                w[q] = wv.x; w[q + 1] = wv.y; w[q + 2] = wv.z; w[q + 3] = wv.w;
            }
#pragma unroll
            for (int i = 0; i < 4; i++)
#pragma unroll
                for (int j = 0; j < TN; j++) acc[i][j] += a[i] * w[j];
        }
        __syncthreads();
    }
#pragma unroll
    for (int i = 0; i < 4; i++) {
        int r = m0 + ty * 4 + i;
        if (r < N) {
            __half hb[TN];
#pragma unroll
            for (int j = 0; j < TN; j++) hb[j] = __float2half(acc[i][j]);
            // TN*2 bytes, TN=8 -> 16B aligned, TN=4 -> 8B aligned
            if (TN == 8)
                *(uint4*)(C + (size_t)r * BN + tx * TN) = *(uint4*)hb;
            else
                *(uint2*)(C + (size_t)r * BN + tx * TN) = *(uint2*)hb;
        }
    }
    if (threadIdx.x == 0) atomicMax(&g_t1[slot], gt_ns());
}

// ---------------- Aggregation (128 feat, half in, fp32 out): warp per node ----------------
__global__ __launch_bounds__(256) void k_agg128(const __half* __restrict__ h,
                                                const float* __restrict__ bias,
                                                float* __restrict__ out, int N,
                                                int slot) {
    if (threadIdx.x == 0) atomicMin(&g_t0[slot], gt_ns());
    int node = (blockIdx.x * blockDim.x + threadIdx.x) >> 5;
    if (node < N) {
        int lane = threadIdx.x & 31;
        const uint2* h2 = (const uint2*)h;  // row = 32 x uint2 (4 halfs per lane)
        int beg = g_rowptr[node], end = g_rowptr[node + 1];

        float ax = 0, ay = 0, az = 0, aw = 0;
        float bx = 0, by = 0, bz = 0, bw = 0;
        int e = beg;
        for (; e + 8 <= end; e += 8) {
            int s[8];
#pragma unroll
            for (int q = 0; q < 8; q++) s[q] = g_esrc[e + q];
            float wgt[8];
#pragma unroll
            for (int q = 0; q < 8; q++) wgt[q] = g_dinv[s[q]];
            uint2 raw[8];
#pragma unroll
            for (int q = 0; q < 8; q++) raw[q] = h2[(size_t)s[q] * 32 + lane];
#pragma unroll
            for (int q = 0; q < 8; q += 2) {
                float2 f0 = __half22float2(*(__half2*)&raw[q].x);
                float2 f1 = __half22float2(*(__half2*)&raw[q].y);
                ax += wgt[q] * f0.x; ay += wgt[q] * f0.y;
                az += wgt[q] * f1.x; aw += wgt[q] * f1.y;
                float2 g0 = __half22float2(*(__half2*)&raw[q + 1].x);
                float2 g1 = __half22float2(*(__half2*)&raw[q + 1].y);
                bx += wgt[q + 1] * g0.x; by += wgt[q + 1] * g0.y;
                bz += wgt[q + 1] * g1.x; bw += wgt[q + 1] * g1.y;
            }
        }
        for (; e < end; e++) {
            int s0 = g_esrc[e];
            float w0 = g_dinv[s0];
            uint2 r0 = h2[(size_t)s0 * 32 + lane];
            float2 f0 = __half22float2(*(__half2*)&r0.x);
            float2 f1 = __half22float2(*(__half2*)&r0.y);
            ax += w0 * f0.x; ay += w0 * f0.y; az += w0 * f1.x; aw += w0 * f1.y;
        }
        float dd = g_dinv[node];
        uint2 rs = h2[(size_t)node * 32 + lane];
        float2 s0 = __half22float2(*(__half2*)&rs.x);
        float2 s1 = __half22float2(*(__half2*)&rs.y);
        ax += bx + dd * s0.x;
        ay += by + dd * s0.y;
        az += bz + dd * s1.x;
        aw += bw + dd * s1.y;
        float4 bb = ((const float4*)bias)[lane];
        float4 o;
        o.x = fmaxf(dd * ax + bb.x, 0.f);
        o.y = fmaxf(dd * ay + bb.y, 0.f);
        o.z = fmaxf(dd * az + bb.z, 0.f);
        o.w = fmaxf(dd * aw + bb.w, 0.f);
        ((float4*)out)[(size_t)node * 32 + lane] = o;
    }
    if (threadIdx.x == 0) atomicMax(&g_t1[slot], gt_ns());
}

// ---------------- Aggregation (40 feat, half in, stride 64) + log_softmax ----------------
__global__ __launch_bounds__(256) void k_agg40(const __half* __restrict__ h,
                                               const float* __restrict__ bias,
                                               float* __restrict__ out, int N) {
    if (threadIdx.x == 0) atomicMin(&g_t0[7], gt_ns());
    int node = (blockIdx.x * blockDim.x + threadIdx.x) >> 5;
    if (node < N) {
        int lane = threadIdx.x & 31;
        const unsigned* h1 = (const unsigned*)h;  // row = 32 x half2 (cols 2l, 2l+1)
        int beg = g_rowptr[node], end = g_rowptr[node + 1];
        float a0 = 0.f, a1 = 0.f;
        int e = beg;
        for (; e + 4 <= end; e += 4) {
            int s[4];
#pragma unroll
            for (int q = 0; q < 4; q++) s[q] = g_esrc[e + q];
            float wgt[4];
#pragma unroll
            for (int q = 0; q < 4; q++) wgt[q] = g_dinv[s[q]];
            unsigned raw[4];
#pragma unroll
            for (int q = 0; q < 4; q++) raw[q] = h1[(size_t)s[q] * 32 + lane];
#pragma unroll
            for (int q = 0; q < 4; q++) {
                float2 f = __half22float2(*(__half2*)&raw[q]);
                a0 += wgt[q] * f.x;
                a1 += wgt[q] * f.y;
            }
        }
        for (; e < end; e++) {
            int s0 = g_esrc[e];
            float wv = g_dinv[s0];
            float2 f = __half22float2(*(__half2*)&h1[(size_t)s0 * 32 + lane]);
            a0 += wv * f.x;
            a1 += wv * f.y;
        }
        float dd = g_dinv[node];
        float2 fs = __half22float2(*(__half2*)&h1[(size_t)node * 32 + lane]);
        a0 += dd * fs.x;
        a1 += dd * fs.y;
        float l0 = -3.4e38f, l1 = -3.4e38f;
        if (lane < 20) {
            l0 = dd * a0 + bias[2 * lane];
            l1 = dd * a1 + bias[2 * lane + 1];
        }
        float m = fmaxf(l0, l1);
#pragma unroll
        for (int o = 16; o; o >>= 1) m = fmaxf(m, __shfl_xor_sync(0xffffffffu, m, o));
        float s = (lane < 20) ? (expf(l0 - m) + expf(l1 - m)) : 0.f;
#pragma unroll
        for (int o = 16; o; o >>= 1) s += __shfl_xor_sync(0xffffffffu, s, o);
        float ls = logf(s);
        if (lane < 20) {
            out[(size_t)node * 40 + 2 * lane] = l0 - m - ls;
            out[(size_t)node * 40 + 2 * lane + 1] = l1 - m - ls;
        }
    }
    if (threadIdx.x == 0) atomicMax(&g_t1[7], gt_ns());
}

// ---------------- host launcher ----------------
extern "C" void kernel_launch(void* const* d_in, const int* in_sizes, int n_in,
                              void* d_out, int out_size) {
    const float* x = (const float*)d_in[0];
    const void* ei = d_in[1];
    const float* W1 = (const float*)d_in[2];
    const float* b1 = (const float*)d_in[3];
    const float* W2 = (const float*)d_in[4];
    const float* b2 = (const float*)d_in[5];
    const float* W3 = (const float*)d_in[6];
    const float* b3 = (const float*)d_in[7];

    int N = in_sizes[0] / 128;
    int E = in_sizes[1] / 2;

    int NB = (N + 511) / 512;
    int EB = (E + 255) / 256;
    int GB = (N + 63) / 64;
    int AB = (N + 7) / 8;

    k_detect_zero<<<NB, 512>>>((const int*)ei, 64, N);
    k_hist<<<EB, 256>>>(ei, E, N);
    k_dinv<<<NB, 512>>>(N);
    k_synth_gather<<<AB, 256>>>(g_hA, g_bufB, N);   // ncu capture slot (#4)
    k_scan1<<<NB, 512>>>(N);
    k_scan2<<<1, 256>>>(NB);
    k_scan3<<<NB, 512>>>(N, E);
    k_scatter<<<EB, 256>>>(ei, E, N);

    // Layer 1: gemm fp32->half, agg half->fp32 (+bias+relu)
    k_gemm<128, 8><<<GB, 256>>>(x, W1, g_hA, N, 128, 2);
    k_agg128<<<AB, 256>>>(g_hA, b1, g_bufB, N, 3);
    // Layer 2
    k_gemm<128, 8><<<GB, 256>>>(g_bufB, W2, g_hA, N, 128, 4);
    k_agg128<<<AB, 256>>>(g_hA, b2, g_bufB, N, 5);
    // Layer 3 + log_softmax
    k_gemm<64, 4><<<GB, 256>>>(g_bufB, W3, g_h3h, N, 40, 6);
    k_agg40<<<AB, 256>>>(g_h3h, b3, (float*)d_out, N);
    k_prof_print<<<1, 32>>>();
}

// round 9
// speedup vs baseline: 4.2102x; 1.5412x over previous
#include <cuda_runtime.h>
#include <cuda_fp16.h>
#include <math.h>

// Problem shape: N=100000, E=1600000, F=H1=H2=128, C=40
#define NN 100000
#define EE 1600000

__device__ __half g_hA[(size_t)NN * 128];   // gemm1/gemm2 output (half)
__device__ __half g_hB[(size_t)NN * 128];   // agg output (half), gemm2/3 input
__device__ __half g_h3h[(size_t)NN * 64];   // layer-3 gemm out, packed stride 40
__device__ float  g_dinv[NN];
__device__ int    g_rowptr[NN + 1];
__device__ int    g_cursor[NN];
__device__ int    g_esrc[EE];
__device__ int    g_partials[256];
__device__ int    g_is64;

// ---------------- dtype detect + zero counts ----------------
__global__ void k_detect_zero(const int* __restrict__ ei32, int n_check, int N) {
    int i = blockIdx.x * blockDim.x + threadIdx.x;
    if (i < N) g_cursor[i] = 0;
    if (i == 0) {
        int is64 = 1;
        for (int t = 0; t < n_check; t++)
            if (ei32[2 * t + 1] != 0) { is64 = 0; break; }
        g_is64 = is64;
    }
}

__device__ __forceinline__ int load_idx(const void* ei, long long pos) {
    return g_is64 ? (int)((const long long*)ei)[pos] : ((const int*)ei)[pos];
}

__global__ void k_hist(const void* __restrict__ ei, int E, int N) {
    int e = blockIdx.x * blockDim.x + threadIdx.x;
    if (e < E) {
        int d = load_idx(ei, (long long)E + e);
        if ((unsigned)d < (unsigned)N) atomicAdd(&g_cursor[d], 1);
    }
}

__global__ void k_dinv(int N) {
    int i = blockIdx.x * blockDim.x + threadIdx.x;
    if (i < N) g_dinv[i] = rsqrtf((float)(g_cursor[i] + 1));
}

template <int NT>
__device__ __forceinline__ int block_exscan(int v) {
    __shared__ int ws[NT / 32];
    int lane = threadIdx.x & 31, wid = threadIdx.x >> 5;
    int x = v;
#pragma unroll
    for (int o = 1; o < 32; o <<= 1) {
        int y = __shfl_up_sync(0xffffffffu, x, o);
        if (lane >= o) x += y;
    }
    if (lane == 31) ws[wid] = x;
    __syncthreads();
    if (wid == 0) {
        int w = (lane < NT / 32) ? ws[lane] : 0;
#pragma unroll
        for (int o = 1; o < 32; o <<= 1) {
            int y = __shfl_up_sync(0xffffffffu, w, o);
            if (lane >= o) w += y;
        }
        if (lane < NT / 32) ws[lane] = w;
    }
    __syncthreads();
    int base = wid ? ws[wid - 1] : 0;
    return base + x - v;
}

__global__ void k_scan1(int N) {
    int gid = blockIdx.x * 512 + threadIdx.x;
    int v = (gid < N) ? g_cursor[gid] : 0;
    int ex = block_exscan<512>(v);
    if (gid < N) g_rowptr[gid] = ex;
    if (threadIdx.x == 511) g_partials[blockIdx.x] = ex + v;
}

__global__ void k_scan2(int NB) {
    int v = (threadIdx.x < NB) ? g_partials[threadIdx.x] : 0;
    int ex = block_exscan<256>(v);
    if (threadIdx.x < NB) g_partials[threadIdx.x] = ex;
}

__global__ void k_scan3(int N, int E) {
    int gid = blockIdx.x * 512 + threadIdx.x;
    if (gid < N) {
        int r = g_rowptr[gid] + g_partials[blockIdx.x];
        g_rowptr[gid] = r;
        g_cursor[gid] = r;
    }
    if (gid == 0) g_rowptr[N] = E;
}

__global__ void k_scatter(const void* __restrict__ ei, int E, int N) {
    int e = blockIdx.x * blockDim.x + threadIdx.x;
    if (e < E) {
        int s = load_idx(ei, e);
        int d = load_idx(ei, (long long)E + e);
        if ((unsigned)d < (unsigned)N && (unsigned)s < (unsigned)N) {
            int p = atomicAdd(&g_cursor[d], 1);
            if ((unsigned)p < (unsigned)EE) g_esrc[p] = s;
        }
    }
}

// ---------------- GEMM: C_half = A @ W, A fp32 or half, fp32 accumulate ----------
// 64xBN tile, 256 threads, 4xTN micro-tile, K chunk 32.
// out_stride/out_cols support packed layer-3 output (stride 40).
template <typename TA, int BN, int TN>
__global__ __launch_bounds__(256, 3) void k_gemm(const TA* __restrict__ A,
                                                 const float* __restrict__ W,
                                                 __half* __restrict__ C, int N, int KW,
                                                 int out_stride, int out_cols) {
    __shared__ float As[64 * 36];
    __shared__ float Ws[32 * (BN + 4)];
    const int WSP = BN + 4;
    int tid = threadIdx.x;
    int tx = tid & 15, ty = tid >> 4;
    int m0 = blockIdx.x * 64;

    float acc[4][TN];
#pragma unroll
    for (int i = 0; i < 4; i++)
#pragma unroll
        for (int j = 0; j < TN; j++) acc[i][j] = 0.f;

    for (int kc = 0; kc < 128; kc += 32) {
        if (sizeof(TA) == 4) {
            // fp32 A: 64 rows x 32 k = 512 float4, 2 per thread
#pragma unroll
            for (int t = 0; t < 2; t++) {
                int idx = tid + t * 256;
                int r = idx >> 3;
                int c4 = (idx & 7) * 4;
                float4 v = make_float4(0.f, 0.f, 0.f, 0.f);
                if (m0 + r < N)
                    v = *(const float4*)((const float*)A + (size_t)(m0 + r) * 128 + kc + c4);
                *(float4*)&As[r * 36 + c4] = v;
            }
        } else {
            // half A: 64 rows x 32 k halfs; 4 threads/row, uint4 = 8 halfs each
            int r = tid >> 2;
            int part = tid & 3;
            uint4 raw = make_uint4(0, 0, 0, 0);
            if (m0 + r < N)
                raw = *(const uint4*)((const __half*)A + (size_t)(m0 + r) * 128 + kc + part * 8);
            const __half2* hp = (const __half2*)&raw;
            float f[8];
#pragma unroll
            for (int i = 0; i < 4; i++) {
                float2 ff = __half22float2(hp[i]);
                f[2 * i] = ff.x;
                f[2 * i + 1] = ff.y;
            }
            *(float4*)&As[r * 36 + part * 8] = make_float4(f[0], f[1], f[2], f[3]);
            *(float4*)&As[r * 36 + part * 8 + 4] = make_float4(f[4], f[5], f[6], f[7]);
        }
        if (KW == BN) {
#pragma unroll
            for (int t = 0; t < (32 * BN) / 1024; t++) {
                int idx = tid + t * 256;
                int k = idx / (BN / 4);
                int c4 = (idx % (BN / 4)) * 4;
                float4 v = *(const float4*)(W + (size_t)(kc + k) * KW + c4);
                *(float4*)&Ws[k * WSP + c4] = v;
            }
        } else {
#pragma unroll
            for (int t = 0; t < (32 * BN) / 256; t++) {
                int idx = tid + t * 256;
                int k = idx / BN, c = idx % BN;
                Ws[k * WSP + c] = (c < KW) ? W[(size_t)(kc + k) * KW + c] : 0.f;
            }
        }
        __syncthreads();
#pragma unroll 4
        for (int k = 0; k < 32; k++) {
            float a[4];
#pragma unroll
            for (int i = 0; i < 4; i++) a[i] = As[(ty * 4 + i) * 36 + k];
            float w[TN];
#pragma unroll
            for (int q = 0; q < TN; q += 4) {
                float4 wv = *(const float4*)&Ws[k * WSP + tx * TN + q];
                w[q] = wv.x; w[q + 1] = wv.y; w[q + 2] = wv.z; w[q + 3] = wv.w;
            }
#pragma unroll
            for (int i = 0; i < 4; i++)
#pragma unroll
                for (int j = 0; j < TN; j++) acc[i][j] += a[i] * w[j];
        }
        __syncthreads();
    }
#pragma unroll
    for (int i = 0; i < 4; i++) {
        int r = m0 + ty * 4 + i;
        int c0 = tx * TN;
        if (r < N && c0 < out_cols) {
            __half hb[TN];
#pragma unroll
            for (int j = 0; j < TN; j++) hb[j] = __float2half(acc[i][j]);
            if (TN == 8)
                *(uint4*)(C + (size_t)r * out_stride + c0) = *(uint4*)hb;
            else
                *(uint2*)(C + (size_t)r * out_stride + c0) = *(uint2*)hb;
        }
    }
}

// ---------------- Aggregation (128 feat, half in, HALF out): warp per node ------
__global__ __launch_bounds__(256) void k_agg128(const __half* __restrict__ h,
                                                const float* __restrict__ bias,
                                                __half* __restrict__ out, int N) {
    int node = (blockIdx.x * blockDim.x + threadIdx.x) >> 5;
    if (node >= N) return;
    int lane = threadIdx.x & 31;
    const uint2* h2 = (const uint2*)h;  // row = 32 x uint2 (4 halfs per lane)
    int beg = g_rowptr[node], end = g_rowptr[node + 1];

    float ax = 0, ay = 0, az = 0, aw = 0;
    float bx = 0, by = 0, bz = 0, bw = 0;
    int e = beg;
    for (; e + 8 <= end; e += 8) {
        int s[8];
#pragma unroll
        for (int q = 0; q < 8; q++) s[q] = g_esrc[e + q];
        float wgt[8];
#pragma unroll
        for (int q = 0; q < 8; q++) wgt[q] = g_dinv[s[q]];
        uint2 raw[8];
#pragma unroll
        for (int q = 0; q < 8; q++) raw[q] = h2[(size_t)s[q] * 32 + lane];
#pragma unroll
        for (int q = 0; q < 8; q += 2) {
            float2 f0 = __half22float2(*(__half2*)&raw[q].x);
            float2 f1 = __half22float2(*(__half2*)&raw[q].y);
            ax += wgt[q] * f0.x; ay += wgt[q] * f0.y;
            az += wgt[q] * f1.x; aw += wgt[q] * f1.y;
            float2 g0 = __half22float2(*(__half2*)&raw[q + 1].x);
            float2 g1 = __half22float2(*(__half2*)&raw[q + 1].y);
            bx += wgt[q + 1] * g0.x; by += wgt[q + 1] * g0.y;
            bz += wgt[q + 1] * g1.x; bw += wgt[q + 1] * g1.y;
        }
    }
    for (; e < end; e++) {
        int s0 = g_esrc[e];
        float w0 = g_dinv[s0];
        uint2 r0 = h2[(size_t)s0 * 32 + lane];
        float2 f0 = __half22float2(*(__half2*)&r0.x);
        float2 f1 = __half22float2(*(__half2*)&r0.y);
        ax += w0 * f0.x; ay += w0 * f0.y; az += w0 * f1.x; aw += w0 * f1.y;
    }
    float dd = g_dinv[node];
    uint2 rs = h2[(size_t)node * 32 + lane];
    float2 s0 = __half22float2(*(__half2*)&rs.x);
    float2 s1 = __half22float2(*(__half2*)&rs.y);
    ax += bx + dd * s0.x;
    ay += by + dd * s0.y;
    az += bz + dd * s1.x;
    aw += bw + dd * s1.y;
    float4 bb = ((const float4*)bias)[lane];
    float ox = fmaxf(dd * ax + bb.x, 0.f);
    float oy = fmaxf(dd * ay + bb.y, 0.f);
    float oz = fmaxf(dd * az + bb.z, 0.f);
    float ow = fmaxf(dd * aw + bb.w, 0.f);
    __half2 p0 = __floats2half2_rn(ox, oy);
    __half2 p1 = __floats2half2_rn(oz, ow);
    uint2 pk;
    pk.x = *(unsigned*)&p0;
    pk.y = *(unsigned*)&p1;
    ((uint2*)out)[(size_t)node * 32 + lane] = pk;
}

// ---------------- Aggregation (40 feat, packed stride 40) + log_softmax ---------
__global__ __launch_bounds__(256) void k_agg40(const __half* __restrict__ h,
                                               const float* __restrict__ bias,
                                               float* __restrict__ out, int N) {
    int node = (blockIdx.x * blockDim.x + threadIdx.x) >> 5;
    if (node >= N) return;
    int lane = threadIdx.x & 31;
    const unsigned* h1 = (const unsigned*)h;  // half2 units, row stride 20
    int beg = g_rowptr[node], end = g_rowptr[node + 1];
    bool act = lane < 20;
    float a0 = 0.f, a1 = 0.f;
    int e = beg;
    for (; e + 4 <= end; e += 4) {
        int s[4];
#pragma unroll
        for (int q = 0; q < 4; q++) s[q] = g_esrc[e + q];
        float wgt[4];
#pragma unroll
        for (int q = 0; q < 4; q++) wgt[q] = g_dinv[s[q]];
        unsigned raw[4];
#pragma unroll
        for (int q = 0; q < 4; q++) raw[q] = act ? h1[(size_t)s[q] * 20 + lane] : 0u;
#pragma unroll
        for (int q = 0; q < 4; q++) {
            float2 f = __half22float2(*(__half2*)&raw[q]);
            a0 += wgt[q] * f.x;
            a1 += wgt[q] * f.y;
        }
    }
    for (; e < end; e++) {
        int s0 = g_esrc[e];
        float wv = g_dinv[s0];
        unsigned r0 = act ? h1[(size_t)s0 * 20 + lane] : 0u;
        float2 f = __half22float2(*(__half2*)&r0);
        a0 += wv * f.x;
        a1 += wv * f.y;
    }
    float dd = g_dinv[node];
    unsigned rs = act ? h1[(size_t)node * 20 + lane] : 0u;
    float2 fs = __half22float2(*(__half2*)&rs);
    a0 += dd * fs.x;
    a1 += dd * fs.y;
    float l0 = -3.4e38f, l1 = -3.4e38f;
    if (act) {
        l0 = dd * a0 + bias[2 * lane];
        l1 = dd * a1 + bias[2 * lane + 1];
    }
    float m = fmaxf(l0, l1);
#pragma unroll
    for (int o = 16; o; o >>= 1) m = fmaxf(m, __shfl_xor_sync(0xffffffffu, m, o));
    float s = act ? (expf(l0 - m) + expf(l1 - m)) : 0.f;
#pragma unroll
    for (int o = 16; o; o >>= 1) s += __shfl_xor_sync(0xffffffffu, s, o);
    float ls = logf(s);
    if (act) {
        out[(size_t)node * 40 + 2 * lane] = l0 - m - ls;
        out[(size_t)node * 40 + 2 * lane + 1] = l1 - m - ls;
    }
}

// ---------------- host launcher ----------------
extern "C" void kernel_launch(void* const* d_in, const int* in_sizes, int n_in,
                              void* d_out, int out_size) {
    const float* x = (const float*)d_in[0];
    const void* ei = d_in[1];
    const float* W1 = (const float*)d_in[2];
    const float* b1 = (const float*)d_in[3];
    const float* W2 = (const float*)d_in[4];
    const float* b2 = (const float*)d_in[5];
    const float* W3 = (const float*)d_in[6];
    const float* b3 = (const float*)d_in[7];

    int N = in_sizes[0] / 128;
    int E = in_sizes[1] / 2;

    int NB = (N + 511) / 512;
    int EB = (E + 255) / 256;
    int GB = (N + 63) / 64;
    int AB = (N + 7) / 8;

    k_detect_zero<<<NB, 512>>>((const int*)ei, 64, N);
    k_hist<<<EB, 256>>>(ei, E, N);
    k_dinv<<<NB, 512>>>(N);
    k_gemm<float, 128, 8><<<GB, 256>>>(x, W1, g_hA, N, 128, 128, 128);  // ncu slot #4
    k_scan1<<<NB, 512>>>(N);
    k_scan2<<<1, 256>>>(NB);
    k_scan3<<<NB, 512>>>(N, E);
    k_scatter<<<EB, 256>>>(ei, E, N);

    k_agg128<<<AB, 256>>>(g_hA, b1, g_hB, N);
    k_gemm<__half, 128, 8><<<GB, 256>>>(g_hB, W2, g_hA, N, 128, 128, 128);
    k_agg128<<<AB, 256>>>(g_hA, b2, g_hB, N);
    k_gemm<__half, 64, 4><<<GB, 256>>>(g_hB, W3, g_h3h, N, 40, 40, 40);
    k_agg40<<<AB, 256>>>(g_h3h, b3, (float*)d_out, N);
}